// round 7
// baseline (speedup 1.0000x reference)
#include <cuda_runtime.h>
#include <cuda_bf16.h>

// Problem constants
#define B_    8
#define N_    8192
#define DIN   13
#define M_    2048
#define KNB   32
#define R2    0.04f

// Output layout (single float32 buffer, outputs concatenated in return order):
//   x_out  [B][M][128]  floats
//   pos_s  [B][M][3]    floats
//   batch_s[B][M]       floats (values 0..7, exact)
#define X_OUT_OFF 0
#define POS_S_OFF (B_ * M_ * 128)            // 2097152
#define BATCH_OFF (POS_S_OFF + B_ * M_ * 3)  // 2146304

// ---------------------------------------------------------------------------
// Distance with NO fma contraction: must bit-match jnp.sum((a-b)**2, -1)
// ---------------------------------------------------------------------------
__device__ __forceinline__ float d2_exact(float ax, float ay, float az,
                                          float bx, float by, float bz) {
    float dx = ax - bx, dy = ay - by, dz = az - bz;
    return __fadd_rn(__fadd_rn(__fmul_rn(dx, dx), __fmul_rn(dy, dy)),
                     __fmul_rn(dz, dz));
}

__device__ __forceinline__ unsigned smem_u32(const void* p) {
    return (unsigned)__cvta_generic_to_shared(p);
}

// Packed f32x2 helpers (Blackwell; ptxas never emits FFMA2 from C++)
__device__ __forceinline__ unsigned long long pack2(float lo, float hi) {
    unsigned long long r;
    asm("mov.b64 %0, {%1, %2};" : "=l"(r) : "f"(lo), "f"(hi));
    return r;
}
__device__ __forceinline__ unsigned long long ffma2(unsigned long long a,
                                                    unsigned long long b,
                                                    unsigned long long c) {
    unsigned long long d;
    asm("fma.rn.f32x2 %0, %1, %2, %3;" : "=l"(d) : "l"(a), "l"(b), "l"(c));
    return d;
}
__device__ __forceinline__ float2 unpack2(unsigned long long v) {
    float lo, hi;
    asm("mov.b64 {%0, %1}, %2;" : "=f"(lo), "=f"(hi) : "l"(v));
    return make_float2(lo, hi);
}

// ===========================================================================
// Kernel A: farthest point sampling, cluster of 8 CTAs per batch element.
// 8 CTAs x 256 threads, 4 points/thread in registers.
// Per iteration (mbarrier-free, no block barrier):
//   - per-thread update + argmax (tie -> smallest index)
//   - warp redux (max valbits; min index among ties)
//   - lanes 0..7 of EVERY warp store the warp winner, packed as
//       [val:32 | (8191-idx):13 | iter:19]
//     into slot[rank*8+wid] of every peer CTA via st.relaxed.cluster
//   - every lane spin-polls 2 of the 64 local slots until tag==iter,
//     64-bit unsigned max (exact: val desc, then min index), then
//     redux over the warp.
// WAR safety (double-buffered slots): a CTA's store for phase p+2 is
// data-dependent (through q and the mind update) on its read of the slot
// it overwrites at phase p, so the read has completed before the store is
// issued anywhere. The tag inside the b64 word makes each poll self-
// validating; deterministic inputs make even stale-replay values benign,
// and slots are zeroed before the opening cluster barrier anyway.
// ===========================================================================
#define FPS_CTAS 8
#define FPS_THR  256
#define FPS_TOT  (FPS_CTAS * FPS_THR)   // 2048
#define FPS_PPT  (N_ / FPS_TOT)         // 4
#define NSLOT    (FPS_CTAS * (FPS_THR / 32))   // 64

__global__ void __launch_bounds__(FPS_THR)
__cluster_dims__(FPS_CTAS, 1, 1)
fps_kernel(const float* __restrict__ pos, float* __restrict__ out) {
    const int rank = blockIdx.x % FPS_CTAS;
    const int b    = blockIdx.x / FPS_CTAS;
    const int tid  = threadIdx.x;
    const int lane = tid & 31;
    const int wid  = tid >> 5;
    const float* posb = pos + (size_t)b * N_ * 3;

    __shared__ unsigned long long s_slot[2][NSLOT];

    if (tid < NSLOT) { s_slot[0][tid] = 0ull; s_slot[1][tid] = 0ull; }
    __syncthreads();
    // All slots zeroed in every CTA before any peer may store into them.
    asm volatile("barrier.cluster.arrive.aligned;" ::: "memory");
    asm volatile("barrier.cluster.wait.aligned;" ::: "memory");

    float px[FPS_PPT], py[FPS_PPT], pz[FPS_PPT], mind[FPS_PPT];
    const int tg = rank * FPS_THR + tid;    // thread id within the cloud
#pragma unroll
    for (int k = 0; k < FPS_PPT; k++) {
        int g = tg + k * FPS_TOT;
        px[k]   = posb[g * 3 + 0];
        py[k]   = posb[g * 3 + 1];
        pz[k]   = posb[g * 3 + 2];
        mind[k] = 1e10f;
    }

    // First sample is index 0.
    float qx = posb[0], qy = posb[1], qz = posb[2];
    if (rank == 0 && tid == 0) {
        size_t o = POS_S_OFF + ((size_t)b * M_) * 3;
        out[o + 0] = qx; out[o + 1] = qy; out[o + 2] = qz;
        out[BATCH_OFF + (size_t)b * M_] = (float)b;
    }

    // Poll addresses for this lane (2 of 64 slots), both buffers.
    const unsigned pa0[2] = { smem_u32(&s_slot[0][lane]),
                              smem_u32(&s_slot[1][lane]) };
    const unsigned pa1[2] = { smem_u32(&s_slot[0][lane + 32]),
                              smem_u32(&s_slot[1][lane + 32]) };
    const unsigned myslot[2] = { smem_u32(&s_slot[0][rank * 8 + wid]),
                                 smem_u32(&s_slot[1][rank * 8 + wid]) };

    for (int it = 1; it < M_; it++) {
        const int buf = it & 1;

        // --- per-thread update + argmax (smallest index on ties) ----------
        float bv = -1.0f; int bi = 0;
#pragma unroll
        for (int k = 0; k < FPS_PPT; k++) {
            float d  = d2_exact(px[k], py[k], pz[k], qx, qy, qz);
            float mv = fminf(mind[k], d);
            mind[k]  = mv;
            if (mv > bv) { bv = mv; bi = tg + k * FPS_TOT; }
        }
        unsigned vb = __float_as_uint(bv);   // bv >= 0 -> monotonic bits

        // --- warp reduce: max value, min index among ties ------------------
        unsigned wmax = __reduce_max_sync(0xffffffffu, vb);
        unsigned cand = (vb == wmax) ? (unsigned)bi : 0xffffffffu;
        unsigned wi   = __reduce_min_sync(0xffffffffu, cand);

        // --- broadcast warp winner to all 8 peer CTAs (lanes 0..7) ---------
        const unsigned long long key =
            ((unsigned long long)wmax << 32) |
            ((unsigned long long)(8191u - wi) << 19) | (unsigned)it;
        if (lane < FPS_CTAS) {
            asm volatile(
                "{\n\t.reg .b32 ra;\n\t"
                "mapa.shared::cluster.u32 ra, %0, %2;\n\t"
                "st.relaxed.cluster.shared::cluster.b64 [ra], %1;\n\t"
                "}"
                :: "r"(myslot[buf]), "l"(key), "r"(lane) : "memory");
        }

        // --- poll the 2 slots owned by this lane until tag == it -----------
        const unsigned tag = (unsigned)it;
        unsigned long long v0, v1;
        do {
            asm volatile("ld.relaxed.cluster.shared::cta.b64 %0, [%1];"
                         : "=l"(v0) : "r"(pa0[buf]) : "memory");
        } while (((unsigned)v0 & 0x7FFFFu) != tag);
        do {
            asm volatile("ld.relaxed.cluster.shared::cta.b64 %0, [%1];"
                         : "=l"(v1) : "r"(pa1[buf]) : "memory");
        } while (((unsigned)v1 & 0x7FFFFu) != tag);

        // --- final reduce: 64-bit unsigned max == (val desc, idx asc) ------
        unsigned long long loc = (v0 > v1) ? v0 : v1;
        unsigned hi = (unsigned)(loc >> 32);
        unsigned lo = (unsigned)loc;
        unsigned vmax = __reduce_max_sync(0xffffffffu, hi);
        unsigned lc   = (hi == vmax) ? lo : 0u;
        unsigned lmax = __reduce_max_sync(0xffffffffu, lc);
        const int gidx = 8191 - (int)(lmax >> 19);

        qx = posb[gidx * 3 + 0];   // broadcast load, L1-resident
        qy = posb[gidx * 3 + 1];
        qz = posb[gidx * 3 + 2];
        if (rank == 0 && tid == 0) {
            size_t o = POS_S_OFF + ((size_t)b * M_ + it) * 3;
            out[o + 0] = qx; out[o + 1] = qy; out[o + 2] = qz;
            out[BATCH_OFF + (size_t)b * M_ + it] = (float)b;
        }
    }

    asm volatile("barrier.cluster.arrive.aligned;" ::: "memory");
    asm volatile("barrier.cluster.wait.aligned;" ::: "memory");
}

// ===========================================================================
// Kernel B: radius ball query (first K by index) + gather + 2-layer MLP +
// masked max over neighbors. One warp per center, lane = neighbor slot.
// Layer 2 uses packed fma.rn.f32x2 (2 FMAs/inst) with W2^T rows streamed
// as ulonglong2 (LDS.128). Warp max via redux.sync on value bits.
// ===========================================================================
#define WPB 8   // warps per block

__global__ void __launch_bounds__(WPB * 32)
sa_kernel(const float* __restrict__ x, const float* __restrict__ pos,
          const float* __restrict__ W1, const float* __restrict__ b1,
          const float* __restrict__ W2, const float* __restrict__ b2,
          float* __restrict__ out) {
    __shared__ __align__(16) float sW1[64][16];    // W1^T
    __shared__ float sb1[64];
    __shared__ __align__(16) float sW2[128][64];   // W2^T
    __shared__ float sb2[128];
    __shared__ int   s_nbr[WPB][KNB];

    const int tid = threadIdx.x;
    for (int i = tid; i < 64 * 16; i += WPB * 32) {
        int j = i >> 4, k = i & 15;
        sW1[j][k] = W1[k * 64 + j];
    }
    for (int i = tid; i < 128 * 64; i += WPB * 32) {
        int j = i >> 6, k = i & 63;
        sW2[j][k] = W2[k * 128 + j];
    }
    if (tid < 64)  sb1[tid] = b1[tid];
    if (tid < 128) sb2[tid] = b2[tid];
    __syncthreads();

    const int warp = tid >> 5;
    const int lane = tid & 31;
    const int c    = blockIdx.x * WPB + warp;   // center id, 0..B*M-1
    const int b    = c >> 11;                   // M_ = 2048
    const float* posb = pos + (size_t)b * N_ * 3;
    const float* xb   = x   + (size_t)b * N_ * DIN;

    const float cx = out[POS_S_OFF + (size_t)c * 3 + 0];
    const float cy = out[POS_S_OFF + (size_t)c * 3 + 1];
    const float cz = out[POS_S_OFF + (size_t)c * 3 + 2];

    // --- Ball query: first KNB in-ball points by ascending index ----------
    int count = 0;
    for (int base = 0; base < N_ && count < KNB; base += 32) {
        const int n = base + lane;
        float d = d2_exact(posb[n * 3 + 0], posb[n * 3 + 1], posb[n * 3 + 2],
                           cx, cy, cz);
        const bool within = (d <= R2);
        const unsigned mask = __ballot_sync(0xffffffffu, within);
        const int pre = __popc(mask & ((1u << lane) - 1u));
        if (within && (count + pre) < KNB) s_nbr[warp][count + pre] = n;
        count += __popc(mask);
        if (count > KNB) count = KNB;
    }
    __syncwarp();
    const bool valid = (lane < count);
    const int  nbr   = valid ? s_nbr[warp][lane] : s_nbr[warp][0];

    // --- Gather features ---------------------------------------------------
    float f[16];
#pragma unroll
    for (int k = 0; k < DIN; k++) f[k] = xb[(size_t)nbr * DIN + k];
    f[13] = posb[nbr * 3 + 0] - cx;
    f[14] = posb[nbr * 3 + 1] - cy;
    f[15] = posb[nbr * 3 + 2] - cz;

    // --- Layer 1: 16 -> 64, ReLU; outputs packed in pairs ------------------
    unsigned long long h1p[32];   // h1p[i] = {h1[2i], h1[2i+1]}
#pragma unroll
    for (int j2 = 0; j2 < 32; j2++) {
        float aA = sb1[2 * j2], aB = sb1[2 * j2 + 1];
        const float4* wA = reinterpret_cast<const float4*>(&sW1[2 * j2][0]);
        const float4* wB = reinterpret_cast<const float4*>(&sW1[2 * j2 + 1][0]);
#pragma unroll
        for (int k4 = 0; k4 < 4; k4++) {
            float4 a4 = wA[k4], b4 = wB[k4];
            aA = fmaf(f[4 * k4 + 0], a4.x, aA);
            aA = fmaf(f[4 * k4 + 1], a4.y, aA);
            aA = fmaf(f[4 * k4 + 2], a4.z, aA);
            aA = fmaf(f[4 * k4 + 3], a4.w, aA);
            aB = fmaf(f[4 * k4 + 0], b4.x, aB);
            aB = fmaf(f[4 * k4 + 1], b4.y, aB);
            aB = fmaf(f[4 * k4 + 2], b4.z, aB);
            aB = fmaf(f[4 * k4 + 3], b4.w, aB);
        }
        h1p[j2] = pack2(fmaxf(aA, 0.0f), fmaxf(aB, 0.0f));
    }

    // --- Layer 2: 64 -> 128, ReLU, masked warp-max -------------------------
    float r0, r1, r2, r3;
#pragma unroll
    for (int jo = 0; jo < 4; jo++) {
#pragma unroll 1
        for (int ji = 0; ji < 32; ji++) {
            const int j = jo * 32 + ji;
            unsigned long long acc0 = pack2(sb2[j], 0.0f);
            unsigned long long acc1 = pack2(0.0f, 0.0f);
            const ulonglong2* w =
                reinterpret_cast<const ulonglong2*>(&sW2[j][0]); // 16 entries
#pragma unroll
            for (int k4 = 0; k4 < 8; k4++) {
                ulonglong2 wa = w[k4];       // k pairs 2k4, 2k4+1
                ulonglong2 wb = w[k4 + 8];   // k pairs 16+2k4, 16+2k4+1
                acc0 = ffma2(h1p[2 * k4 + 0],      wa.x, acc0);
                acc1 = ffma2(h1p[2 * k4 + 1],      wa.y, acc1);
                acc0 = ffma2(h1p[16 + 2 * k4 + 0], wb.x, acc0);
                acc1 = ffma2(h1p[16 + 2 * k4 + 1], wb.y, acc1);
            }
            float2 u0 = unpack2(acc0);
            float2 u1 = unpack2(acc1);
            float acc = fmaxf((u0.x + u0.y) + (u1.x + u1.y), 0.0f);
            // invalid slots contribute 0: safe because ReLU >= 0 and the
            // center itself is always a valid neighbor (d^2 = 0 <= R^2).
            if (!valid) acc = 0.0f;
            unsigned red = __reduce_max_sync(0xffffffffu, __float_as_uint(acc));
            if (lane == ji) {
                float rv = __uint_as_float(red);
                if (jo == 0) r0 = rv;
                else if (jo == 1) r1 = rv;
                else if (jo == 2) r2 = rv;
                else r3 = rv;
            }
        }
    }

    float* o = out + X_OUT_OFF + (size_t)c * 128;
    o[lane +  0] = r0;
    o[lane + 32] = r1;
    o[lane + 64] = r2;
    o[lane + 96] = r3;
}

// ===========================================================================
extern "C" void kernel_launch(void* const* d_in, const int* in_sizes, int n_in,
                              void* d_out, int out_size) {
    (void)in_sizes; (void)n_in; (void)out_size;
    const float* x   = (const float*)d_in[0];   // [B, N, 13]
    const float* pos = (const float*)d_in[1];   // [B, N, 3]
    // d_in[2] = batch (int32) — always broadcast arange(B), recomputed directly
    const float* W1  = (const float*)d_in[3];   // [16, 64]
    const float* b1  = (const float*)d_in[4];   // [64]
    const float* W2  = (const float*)d_in[5];   // [64, 128]
    const float* b2  = (const float*)d_in[6];   // [128]
    float* out = (float*)d_out;

    fps_kernel<<<B_ * FPS_CTAS, FPS_THR>>>(pos, out);
    sa_kernel<<<(B_ * M_) / WPB, WPB * 32>>>(x, pos, W1, b1, W2, b2, out);
}

// round 9
// speedup vs baseline: 1.8640x; 1.8640x over previous
#include <cuda_runtime.h>
#include <cuda_bf16.h>

// Problem constants
#define B_    8
#define N_    8192
#define DIN   13
#define M_    2048
#define KNB   32
#define R2    0.04f

// Output layout (single float32 buffer, outputs concatenated in return order):
//   x_out  [B][M][128]  floats
//   pos_s  [B][M][3]    floats
//   batch_s[B][M]       floats (values 0..7, exact)
#define X_OUT_OFF 0
#define POS_S_OFF (B_ * M_ * 128)            // 2097152
#define BATCH_OFF (POS_S_OFF + B_ * M_ * 3)  // 2146304

// ---------------------------------------------------------------------------
// Distance with NO fma contraction: must bit-match jnp.sum((a-b)**2, -1)
// ---------------------------------------------------------------------------
__device__ __forceinline__ float d2_exact(float ax, float ay, float az,
                                          float bx, float by, float bz) {
    float dx = ax - bx, dy = ay - by, dz = az - bz;
    return __fadd_rn(__fadd_rn(__fmul_rn(dx, dx), __fmul_rn(dy, dy)),
                     __fmul_rn(dz, dz));
}

__device__ __forceinline__ unsigned smem_u32(const void* p) {
    return (unsigned)__cvta_generic_to_shared(p);
}

// ===========================================================================
// Kernel A: farthest point sampling, cluster of 8 CTAs per batch element.
// 8 CTAs x 256 threads, 4 points/thread in registers.
// Per iteration (NO __syncthreads, NO block stage):
//   - per-thread update + argmax (tie -> smallest index)
//   - warp redux (max valbits; min index among ties)
//   - lanes 0..7 of EVERY warp store the warp winner, packed as
//       u64 [val:32 | (8191-idx):13]
//     into slot[rank*8+wid] of CTA 'lane' (st.shared::cluster), then
//     mbarrier.arrive.release.cluster on that CTA's mbarrier.
//     Each CTA's mbarrier expects 64 arrivals (one per source warp).
//   - all threads sleep on the local mbarrier (try_wait, parity (it-1)&1),
//     then each lane u64-maxes 2 of the 64 local slots and two redux.sync
//     rounds produce the global winner (u64 max == val desc, idx asc).
// WAR safety (double-buffered slots): a warp's store for phase p+2 is
// preceded in program order by its acquire-wait on phase p+1, which
// synchronizes with every release-arrive of p+1, each of which follows
// (in its thread's program order) that thread's reads of the phase-p slot
// being overwritten. Release covers prior loads, so read-before-overwrite
// is guaranteed.
// ===========================================================================
#define FPS_CTAS  8
#define FPS_THR   256
#define FPS_TOT   (FPS_CTAS * FPS_THR)      // 2048
#define FPS_PPT   (N_ / FPS_TOT)            // 4
#define FPS_WARPS (FPS_THR / 32)            // 8
#define NSLOT     (FPS_CTAS * FPS_WARPS)    // 64

__global__ void __launch_bounds__(FPS_THR)
__cluster_dims__(FPS_CTAS, 1, 1)
fps_kernel(const float* __restrict__ pos, float* __restrict__ out) {
    const int rank = blockIdx.x % FPS_CTAS;
    const int b    = blockIdx.x / FPS_CTAS;
    const int tid  = threadIdx.x;
    const int lane = tid & 31;
    const int wid  = tid >> 5;
    const float* posb = pos + (size_t)b * N_ * 3;

    __shared__ unsigned long long s_mbar;
    __shared__ __align__(16) unsigned long long s_slot[2][NSLOT];

    const unsigned mbar_addr = smem_u32(&s_mbar);
    if (tid == 0) {
        asm volatile("mbarrier.init.shared.b64 [%0], %1;"
                     :: "r"(mbar_addr), "r"(NSLOT) : "memory");
    }
    __syncthreads();
    // All mbarriers initialized cluster-wide before any peer arrives.
    asm volatile("barrier.cluster.arrive.aligned;" ::: "memory");
    asm volatile("barrier.cluster.wait.aligned;" ::: "memory");

    float px[FPS_PPT], py[FPS_PPT], pz[FPS_PPT], mind[FPS_PPT];
    const int tg = rank * FPS_THR + tid;    // thread id within the cloud
#pragma unroll
    for (int k = 0; k < FPS_PPT; k++) {
        int g = tg + k * FPS_TOT;
        px[k]   = posb[g * 3 + 0];
        py[k]   = posb[g * 3 + 1];
        pz[k]   = posb[g * 3 + 2];
        mind[k] = 1e10f;
    }

    // First sample is index 0.
    float qx = posb[0], qy = posb[1], qz = posb[2];
    if (rank == 0 && tid == 0) {
        size_t o = POS_S_OFF + ((size_t)b * M_) * 3;
        out[o + 0] = qx; out[o + 1] = qy; out[o + 2] = qz;
        out[BATCH_OFF + (size_t)b * M_] = (float)b;
    }

    // This warp's slot address (same offset in every CTA), both buffers.
    const unsigned myslot[2] = { smem_u32(&s_slot[0][rank * FPS_WARPS + wid]),
                                 smem_u32(&s_slot[1][rank * FPS_WARPS + wid]) };
    // This lane's two read slots, both buffers (contiguous 16B -> LDS.128).
    const unsigned rdslot[2] = { smem_u32(&s_slot[0][2 * lane]),
                                 smem_u32(&s_slot[1][2 * lane]) };

    for (int it = 1; it < M_; it++) {
        const int buf = it & 1;

        // --- per-thread update + argmax (smallest index on ties) ----------
        float bv = -1.0f; int bi = 0;
#pragma unroll
        for (int k = 0; k < FPS_PPT; k++) {
            float d  = d2_exact(px[k], py[k], pz[k], qx, qy, qz);
            float mv = fminf(mind[k], d);
            mind[k]  = mv;
            if (mv > bv) { bv = mv; bi = tg + k * FPS_TOT; }
        }
        unsigned vb = __float_as_uint(bv);   // bv >= 0 -> monotonic bits

        // --- warp reduce: max value, min index among ties ------------------
        unsigned wmax = __reduce_max_sync(0xffffffffu, vb);
        unsigned cand = (vb == wmax) ? (unsigned)bi : 0xffffffffu;
        unsigned wi   = __reduce_min_sync(0xffffffffu, cand);

        // --- ship warp winner to every CTA; release-arrive their mbarrier --
        const unsigned long long key =
            ((unsigned long long)wmax << 32) | (unsigned)(8191u - wi);
        if (lane < FPS_CTAS) {
            asm volatile(
                "{\n\t.reg .b32 ra, rb;\n\t"
                "mapa.shared::cluster.u32 ra, %0, %2;\n\t"
                "st.shared::cluster.b64 [ra], %1;\n\t"
                "mapa.shared::cluster.u32 rb, %3, %2;\n\t"
                "mbarrier.arrive.release.cluster.shared::cluster.b64 _, [rb];\n\t"
                "}"
                :: "r"(myslot[buf]), "l"(key), "r"(lane), "r"(mbar_addr)
                : "memory");
        }

        // --- sleep until all 64 warp winners have arrived ------------------
        {
            unsigned parity = (unsigned)((it - 1) & 1);
            asm volatile(
                "{\n\t.reg .pred P1;\n\t"
                "WAIT_%=:\n\t"
                "mbarrier.try_wait.parity.acquire.cluster.shared::cta.b64 P1, [%0], %1;\n\t"
                "@P1 bra DONE_%=;\n\t"
                "bra WAIT_%=;\n\t"
                "DONE_%=:\n\t}"
                :: "r"(mbar_addr), "r"(parity) : "memory");
        }

        // --- reduce 64 slots: u64 max == (val desc, idx asc) ---------------
        unsigned long long v0, v1;
        asm volatile("ld.shared.v2.b64 {%0, %1}, [%2];"
                     : "=l"(v0), "=l"(v1) : "r"(rdslot[buf]) : "memory");
        unsigned long long m = (v0 > v1) ? v0 : v1;
        unsigned hi = (unsigned)(m >> 32);
        unsigned lo = (unsigned)m;
        unsigned vmax = __reduce_max_sync(0xffffffffu, hi);
        unsigned lc   = (hi == vmax) ? lo : 0u;
        unsigned lmax = __reduce_max_sync(0xffffffffu, lc);
        const int gidx = 8191 - (int)lmax;

        qx = posb[gidx * 3 + 0];   // broadcast load, L1-resident
        qy = posb[gidx * 3 + 1];
        qz = posb[gidx * 3 + 2];
        if (rank == 0 && tid == 0) {
            size_t o = POS_S_OFF + ((size_t)b * M_ + it) * 3;
            out[o + 0] = qx; out[o + 1] = qy; out[o + 2] = qz;
            out[BATCH_OFF + (size_t)b * M_ + it] = (float)b;
        }
    }

    asm volatile("barrier.cluster.arrive.aligned;" ::: "memory");
    asm volatile("barrier.cluster.wait.aligned;" ::: "memory");
}

// ===========================================================================
// Kernel B: radius ball query (first K by index) + gather + 2-layer MLP +
// masked max over neighbors. One warp per center, lane = neighbor slot.
// (Reverted to the Round-6 version: scalar FMA dual-chain layer 2 +
//  redux.sync max — measured 448 us.)
// ===========================================================================
#define WPB 8   // warps per block

__global__ void __launch_bounds__(WPB * 32)
sa_kernel(const float* __restrict__ x, const float* __restrict__ pos,
          const float* __restrict__ W1, const float* __restrict__ b1,
          const float* __restrict__ W2, const float* __restrict__ b2,
          float* __restrict__ out) {
    __shared__ __align__(16) float sW1[64][16];    // W1^T
    __shared__ float sb1[64];
    __shared__ __align__(16) float sW2[128][64];   // W2^T
    __shared__ float sb2[128];
    __shared__ int   s_nbr[WPB][KNB];

    const int tid = threadIdx.x;
    for (int i = tid; i < 64 * 16; i += WPB * 32) {
        int j = i >> 4, k = i & 15;
        sW1[j][k] = W1[k * 64 + j];
    }
    for (int i = tid; i < 128 * 64; i += WPB * 32) {
        int j = i >> 6, k = i & 63;
        sW2[j][k] = W2[k * 128 + j];
    }
    if (tid < 64)  sb1[tid] = b1[tid];
    if (tid < 128) sb2[tid] = b2[tid];
    __syncthreads();

    const int warp = tid >> 5;
    const int lane = tid & 31;
    const int c    = blockIdx.x * WPB + warp;   // center id, 0..B*M-1
    const int b    = c >> 11;                   // M_ = 2048
    const float* posb = pos + (size_t)b * N_ * 3;
    const float* xb   = x   + (size_t)b * N_ * DIN;

    const float cx = out[POS_S_OFF + (size_t)c * 3 + 0];
    const float cy = out[POS_S_OFF + (size_t)c * 3 + 1];
    const float cz = out[POS_S_OFF + (size_t)c * 3 + 2];

    // --- Ball query: first KNB in-ball points by ascending index ----------
    int count = 0;
    for (int base = 0; base < N_ && count < KNB; base += 32) {
        const int n = base + lane;
        float d = d2_exact(posb[n * 3 + 0], posb[n * 3 + 1], posb[n * 3 + 2],
                           cx, cy, cz);
        const bool within = (d <= R2);
        const unsigned mask = __ballot_sync(0xffffffffu, within);
        const int pre = __popc(mask & ((1u << lane) - 1u));
        if (within && (count + pre) < KNB) s_nbr[warp][count + pre] = n;
        count += __popc(mask);
        if (count > KNB) count = KNB;
    }
    __syncwarp();
    const bool valid = (lane < count);
    const int  nbr   = valid ? s_nbr[warp][lane] : s_nbr[warp][0];

    // --- Gather features ---------------------------------------------------
    float f[16];
#pragma unroll
    for (int k = 0; k < DIN; k++) f[k] = xb[(size_t)nbr * DIN + k];
    f[13] = posb[nbr * 3 + 0] - cx;
    f[14] = posb[nbr * 3 + 1] - cy;
    f[15] = posb[nbr * 3 + 2] - cz;

    // --- Layer 1: 16 -> 64, ReLU (h1 stays in registers) -------------------
    float h1[64];
#pragma unroll
    for (int j = 0; j < 64; j++) {
        float acc = sb1[j];
        const float4* w = reinterpret_cast<const float4*>(&sW1[j][0]);
#pragma unroll
        for (int k4 = 0; k4 < 4; k4++) {
            float4 w4 = w[k4];
            acc = fmaf(f[4 * k4 + 0], w4.x, acc);
            acc = fmaf(f[4 * k4 + 1], w4.y, acc);
            acc = fmaf(f[4 * k4 + 2], w4.z, acc);
            acc = fmaf(f[4 * k4 + 3], w4.w, acc);
        }
        h1[j] = fmaxf(acc, 0.0f);
    }

    // --- Layer 2: 64 -> 128, ReLU, masked warp-max (redux.sync) ------------
    float r0, r1, r2, r3;
#pragma unroll
    for (int jo = 0; jo < 4; jo++) {
#pragma unroll 1
        for (int ji = 0; ji < 32; ji++) {
            const int j = jo * 32 + ji;
            float a0 = sb2[j], a1 = 0.0f;
            const float4* w = reinterpret_cast<const float4*>(&sW2[j][0]);
#pragma unroll
            for (int k4 = 0; k4 < 8; k4++) {
                float4 wA = w[k4];
                float4 wB = w[k4 + 8];
                a0 = fmaf(h1[4 * k4 + 0],      wA.x, a0);
                a0 = fmaf(h1[4 * k4 + 1],      wA.y, a0);
                a0 = fmaf(h1[4 * k4 + 2],      wA.z, a0);
                a0 = fmaf(h1[4 * k4 + 3],      wA.w, a0);
                a1 = fmaf(h1[32 + 4 * k4 + 0], wB.x, a1);
                a1 = fmaf(h1[32 + 4 * k4 + 1], wB.y, a1);
                a1 = fmaf(h1[32 + 4 * k4 + 2], wB.z, a1);
                a1 = fmaf(h1[32 + 4 * k4 + 3], wB.w, a1);
            }
            float acc = fmaxf(a0 + a1, 0.0f);
            // invalid slots contribute 0: safe because ReLU >= 0 and the
            // center itself is always a valid neighbor (d^2 = 0 <= R^2).
            if (!valid) acc = 0.0f;
            // acc >= 0 -> f32 bits monotonic under unsigned max
            unsigned red = __reduce_max_sync(0xffffffffu, __float_as_uint(acc));
            if (lane == ji) {
                float rv = __uint_as_float(red);
                if (jo == 0) r0 = rv;
                else if (jo == 1) r1 = rv;
                else if (jo == 2) r2 = rv;
                else r3 = rv;
            }
        }
    }

    float* o = out + X_OUT_OFF + (size_t)c * 128;
    o[lane +  0] = r0;
    o[lane + 32] = r1;
    o[lane + 64] = r2;
    o[lane + 96] = r3;
}

// ===========================================================================
extern "C" void kernel_launch(void* const* d_in, const int* in_sizes, int n_in,
                              void* d_out, int out_size) {
    (void)in_sizes; (void)n_in; (void)out_size;
    const float* x   = (const float*)d_in[0];   // [B, N, 13]
    const float* pos = (const float*)d_in[1];   // [B, N, 3]
    // d_in[2] = batch (int32) — always broadcast arange(B), recomputed directly
    const float* W1  = (const float*)d_in[3];   // [16, 64]
    const float* b1  = (const float*)d_in[4];   // [64]
    const float* W2  = (const float*)d_in[5];   // [64, 128]
    const float* b2  = (const float*)d_in[6];   // [128]
    float* out = (float*)d_out;

    fps_kernel<<<B_ * FPS_CTAS, FPS_THR>>>(pos, out);
    sa_kernel<<<(B_ * M_) / WPB, WPB * 32>>>(x, pos, W1, b1, W2, b2, out);
}